// round 15
// baseline (speedup 1.0000x reference)
#include <cuda_runtime.h>
#include <cuda_fp16.h>
#include <math.h>

#define Bdim 4
#define Ldim 1024
#define Hdim 16
#define Ddim 64
#define HIDdim 1024
#define BHdim (Bdim*Hdim)

// fp16 copies of GEMM operands (converted once at start)
__device__ __half h_qry[4194304];
__device__ __half h_key[4194304];
__device__ __half h_val[4194304];
__device__ __half h_wq[1048576];
__device__ __half h_wk[1048576];
__device__ __half h_wv[1048576];
__device__ __half h_wo[1048576];
// fp16 intermediates
__device__ __half g_qh[4194304];   // [BH][L][D]
__device__ __half g_kh[4194304];   // [BH][L][D]
__device__ __half g_vh[4194304];   // TRANSPOSED [BH][D][L]
__device__ __half g_atth[4194304]; // [BH][L][D]

__device__ __forceinline__ unsigned f2h2(float lo, float hi) {
    __half2 h = __float22half2_rn(make_float2(lo, hi));
    return *(unsigned*)&h;
}

__device__ __forceinline__ void mma_f16(
    float& c0, float& c1, float& c2, float& c3,
    unsigned a0, unsigned a1, unsigned a2, unsigned a3,
    unsigned b0, unsigned b1)
{
    asm volatile(
        "mma.sync.aligned.m16n8k16.row.col.f32.f16.f16.f32 "
        "{%0,%1,%2,%3}, {%4,%5,%6,%7}, {%8,%9}, {%0,%1,%2,%3};"
        : "+f"(c0), "+f"(c1), "+f"(c2), "+f"(c3)
        : "r"(a0), "r"(a1), "r"(a2), "r"(a3), "r"(b0), "r"(b1));
}

__device__ __forceinline__ void ldsm4(
    unsigned& r0, unsigned& r1, unsigned& r2, unsigned& r3, unsigned addr)
{
    asm volatile("ldmatrix.sync.aligned.m8n8.x4.shared.b16 {%0,%1,%2,%3}, [%4];"
        : "=r"(r0), "=r"(r1), "=r"(r2), "=r"(r3) : "r"(addr));
}

__device__ __forceinline__ void cp16(void* smem, const void* gmem) {
    unsigned sa = (unsigned)__cvta_generic_to_shared(smem);
    asm volatile("cp.async.cg.shared.global [%0], [%1], 16;" :: "r"(sa), "l"(gmem));
}
__device__ __forceinline__ void stcs2(float* p, float x, float y) {
    asm volatile("st.global.cs.v2.f32 [%0], {%1,%2};" :: "l"(p), "f"(x), "f"(y) : "memory");
}
#define CP_COMMIT() asm volatile("cp.async.commit_group;")
#define CP_WAIT0()  asm volatile("cp.async.wait_group 0;")
#define CP_WAIT1()  asm volatile("cp.async.wait_group 1;")

// ---------------------------------------------------------------------------
// fp32 -> fp16 conversion of all GEMM operands. 16M floats, float4/thread.
// ---------------------------------------------------------------------------
__global__ void __launch_bounds__(256) conv_half(
    const float* __restrict__ q, const float* __restrict__ k,
    const float* __restrict__ v,
    const float* __restrict__ wq, const float* __restrict__ wk,
    const float* __restrict__ wv, const float* __restrict__ wo)
{
    const size_t idx = (size_t)blockIdx.x * 256 + threadIdx.x;
    const size_t e = idx * 4;
    const float* src;
    __half* dst;
    size_t off;
    if (e < 4194304)        { src = q;  dst = h_qry; off = e; }
    else if (e < 8388608)   { src = k;  dst = h_key; off = e - 4194304; }
    else if (e < 12582912)  { src = v;  dst = h_val; off = e - 8388608; }
    else {
        const size_t e2 = e - 12582912;
        const int s = (int)(e2 >> 20);
        off = e2 & 1048575;
        src = (s == 0) ? wq : (s == 1) ? wk : (s == 2) ? wv : wo;
        dst = (s == 0) ? h_wq : (s == 1) ? h_wk : (s == 2) ? h_wv : h_wo;
    }
    const float4 f = *(const float4*)(src + off);
    *(__half2*)(dst + off)     = __float22half2_rn(make_float2(f.x, f.y));
    *(__half2*)(dst + off + 2) = __float22half2_rn(make_float2(f.z, f.w));
}

// ---------------------------------------------------------------------------
// fp16 GEMM core (R11 config): block tile 64x128, 128 threads (4 warps,
// warp tile 64x32), K=1024, k-tile 64 halves, double-buffered cp.async,
// ldmatrix feeds. SINGLE barrier per k-iteration.
// ---------------------------------------------------------------------------
#define GEMM_SMEM ((2*64*72 + 2*128*72) * 2)   // 55296 B

struct GemmCoreH {
    float c[4][4][4];

    template<class SrcA>
    __device__ __forceinline__ void run(
        __half* smh, SrcA srcA, const __half* __restrict__ W,
        int M0, int N0, int tid, int wn, int lane)
    {
        __half* As = smh;                 // [2][64][72]
        __half* Ws = smh + 2 * 64 * 72;   // [2][128][72]
        const unsigned uAs = (unsigned)__cvta_generic_to_shared(As);
        const unsigned uWs = (unsigned)__cvta_generic_to_shared(Ws);
        const int quad = lane >> 3, r8 = lane & 7;
        const int aoff = (((quad & 1) << 3) + r8) * 72 + ((quad >> 1) << 3);
        const int boff = (((quad >> 1) << 3) + r8) * 72 + ((quad & 1) << 3);

        #pragma unroll
        for (int mi = 0; mi < 4; mi++)
            #pragma unroll
            for (int ni = 0; ni < 4; ni++)
                #pragma unroll
                for (int r = 0; r < 4; r++) c[mi][ni][r] = 0.f;

        auto issue = [&](int kt, int s) {
            const int k0 = kt * 64;
            #pragma unroll
            for (int p = 0; p < 4; p++) {
                const int cid = tid + p * 128;
                const int m = cid >> 3;
                const int cc = (cid & 7) << 3;
                cp16(&As[(size_t)(s * 64 + m) * 72 + cc], srcA(M0 + m, k0 + cc));
            }
            #pragma unroll
            for (int p = 0; p < 8; p++) {
                const int cid = tid + p * 128;
                const int m = cid >> 3;
                const int cc = (cid & 7) << 3;
                cp16(&Ws[(size_t)(s * 128 + m) * 72 + cc],
                     W + (size_t)(N0 + m) * 1024 + k0 + cc);
            }
            CP_COMMIT();
        };

        issue(0, 0);
        for (int kt = 0; kt < 16; kt++) {
            const int s = kt & 1;
            CP_WAIT0();
            __syncthreads();
            if (kt + 1 < 16) issue(kt + 1, s ^ 1);

            const unsigned aBase = uAs + (unsigned)((s * 64) * 72 + aoff) * 2;
            const unsigned bBase = uWs + (unsigned)((s * 128 + wn * 32) * 72 + boff) * 2;
            #pragma unroll
            for (int ks = 0; ks < 4; ks++) {
                const int kk = ks * 16;
                unsigned af[4][4], bf[4][2];
                #pragma unroll
                for (int mi = 0; mi < 4; mi++)
                    ldsm4(af[mi][0], af[mi][1], af[mi][2], af[mi][3],
                          aBase + (unsigned)(mi * 16 * 72 + kk) * 2);
                #pragma unroll
                for (int np = 0; np < 2; np++)
                    ldsm4(bf[2*np][0], bf[2*np][1], bf[2*np+1][0], bf[2*np+1][1],
                          bBase + (unsigned)(np * 16 * 72 + kk) * 2);
                #pragma unroll
                for (int mi = 0; mi < 4; mi++)
                    #pragma unroll
                    for (int ni = 0; ni < 4; ni++)
                        mma_f16(c[mi][ni][0], c[mi][ni][1], c[mi][ni][2], c[mi][ni][3],
                                af[mi][0], af[mi][1], af[mi][2], af[mi][3],
                                bf[ni][0], bf[ni][1]);
            }
        }
    }
};

// ---------------------------------------------------------------------------
// Merged Q/K/V projection: 1536 blocks of 128 threads, z = g>>9.
// ---------------------------------------------------------------------------
__global__ void __launch_bounds__(128, 4) qkv_gemm(
    const float* __restrict__ Wq_b, const float* __restrict__ Wk_b,
    const float* __restrict__ Wv_b)
{
    extern __shared__ __half smh[];
    const int g = blockIdx.x;
    const int z = g >> 9;
    const int r = g & 511;
    const int tid = threadIdx.x;
    const int lane = tid & 31;
    const int grp = lane >> 2;
    const int tig = lane & 3;
    const int wn = tid >> 5;

    const __half *A, *W;
    const float* bias;
    int M0, N0;
    if (z == 0)      { A = h_qry; W = h_wq; bias = Wq_b; M0 = (r >> 3) * 64; N0 = (r & 7) * 128; }
    else if (z == 1) { A = h_key; W = h_wk; bias = Wk_b; M0 = (r >> 3) * 64; N0 = (r & 7) * 128; }
    else             { A = h_wv;  W = h_val; bias = Wv_b; M0 = (r & 15) * 64; N0 = (r >> 4) * 128; }

    GemmCoreH gc;
    gc.run(smh, [&](int m, int k) { return (const void*)(A + (size_t)m * 1024 + k); },
           W, M0, N0, tid, wn, lane);

    #pragma unroll
    for (int mi = 0; mi < 4; mi++) {
        #pragma unroll
        for (int ni = 0; ni < 4; ni++) {
            const int r0 = M0 + mi * 16 + grp;
            const int r1 = r0 + 8;
            const int cn = N0 + wn * 32 + ni * 8 + tig * 2;
            if (z == 2) {
                const float bv0 = bias[r0], bv1 = bias[r1];
                const size_t base = (size_t)(cn >> 10) * 1048576 + (cn & 1023);
                *(__half2*)(g_vh + base + (size_t)r0 * 1024) =
                    __float22half2_rn(make_float2(gc.c[mi][ni][0] + bv0, gc.c[mi][ni][1] + bv0));
                *(__half2*)(g_vh + base + (size_t)r1 * 1024) =
                    __float22half2_rn(make_float2(gc.c[mi][ni][2] + bv1, gc.c[mi][ni][3] + bv1));
            } else {
                __half* dst = (z == 0) ? g_qh : g_kh;
                const float bv0 = bias[cn], bv1 = bias[cn + 1];
                const int h = cn >> 6, d = cn & 63;
                const int bi0 = r0 >> 10, l0 = r0 & 1023;
                const int bi1 = r1 >> 10, l1 = r1 & 1023;
                *(__half2*)(dst + (((size_t)(bi0 * Hdim + h)) * Ldim + l0) * Ddim + d) =
                    __float22half2_rn(make_float2(gc.c[mi][ni][0] + bv0, gc.c[mi][ni][1] + bv1));
                *(__half2*)(dst + (((size_t)(bi1 * Hdim + h)) * Ldim + l1) * Ddim + d) =
                    __float22half2_rn(make_float2(gc.c[mi][ni][2] + bv0, gc.c[mi][ni][3] + bv1));
            }
        }
    }
}

// ---------------------------------------------------------------------------
// Output projection: out = merge_heads(g_atth) @ Wo^T + bo (fp32 out)
// ---------------------------------------------------------------------------
__global__ void __launch_bounds__(128, 4) out_gemm(
    const float* __restrict__ bias,
    float* __restrict__ Cout)
{
    extern __shared__ __half smh[];
    const int M0 = blockIdx.y * 64;
    const int N0 = blockIdx.x * 128;
    const int tid = threadIdx.x;
    const int lane = tid & 31;
    const int grp = lane >> 2;
    const int tig = lane & 3;
    const int wn = tid >> 5;

    GemmCoreH gc;
    gc.run(smh,
        [&](int m, int k) {
            const int bi = m >> 10, l = m & 1023;
            const int h = k >> 6, d = k & 63;
            return (const void*)(g_atth + (((size_t)(bi * Hdim + h)) * Ldim + l) * Ddim + d);
        },
        h_wo, M0, N0, tid, wn, lane);

    #pragma unroll
    for (int mi = 0; mi < 4; mi++) {
        #pragma unroll
        for (int ni = 0; ni < 4; ni++) {
            const int r0 = M0 + mi * 16 + grp;
            const int r1 = r0 + 8;
            const int cn = N0 + wn * 32 + ni * 8 + tig * 2;
            const float bv0 = bias[cn], bv1 = bias[cn + 1];
            *(float2*)(Cout + (size_t)r0 * 1024 + cn) =
                make_float2(gc.c[mi][ni][0] + bv0, gc.c[mi][ni][1] + bv1);
            *(float2*)(Cout + (size_t)r1 * 1024 + cn) =
                make_float2(gc.c[mi][ni][2] + bv0, gc.c[mi][ni][3] + bv1);
        }
    }
}

// ---------------------------------------------------------------------------
// Fused flash attention: R11 compute (Q in smem), SINGLE-buffered V ->
// smem 54.3KB -> 4 blocks/SM (16 warps). 64-query blocks, 128 threads.
// Per-tile (2 barriers):
//   top: wait0 (P[t],K[t] done) -> sync (V buffer free: PV(t-1) reads done)
//        -> issueV(t) -> issueK(t+1)   [FIFO: V(t), K(t+1)]
//        -> S-mma (V copy in flight underneath)
//   mid: wait1 (V[t] done, K[t+1] may pend) -> sync (V visible)
//        -> epilogue -> P (warp-local) -> PV -> issueP(t+1)
// ---------------------------------------------------------------------------
#define SMEM_FUSED ((2*64*72 + 64*72 + 64*72) * 2 + 64*68*4)   // 54272 B

__global__ void __launch_bounds__(128, 4) fused_attn(
    const float* __restrict__ prev,
    const int* __restrict__ mask,
    const float* __restrict__ gat,
    float* __restrict__ scores)
{
    extern __shared__ __half smh[];
    __half* fKh = smh;                      // [2][64][72] K tiles [j][d]
    __half* uQh = fKh + 2 * 64 * 72;        // [64][72]    Q tile
    __half* fVh = uQh + 64 * 72;            // [64][72]    V^T tile [d][j]
    float*  fP  = (float*)(fVh + 64 * 72);  // [64][68]    prev fp32 / P half2
    unsigned* uP = (unsigned*)fP;

    const unsigned uKb = (unsigned)__cvta_generic_to_shared(fKh);
    const unsigned uQb = (unsigned)__cvta_generic_to_shared(uQh);
    const unsigned uVb = (unsigned)__cvta_generic_to_shared(fVh);
    const unsigned uPb = (unsigned)__cvta_generic_to_shared(fP);

    const int bh = blockIdx.y;
    const int q0 = blockIdx.x * 64;
    const int tid = threadIdx.x;
    const int w = tid >> 5;
    const int lane = tid & 31;
    const int grp = lane >> 2;
    const int tig = lane & 3;
    const int quad = lane >> 3, r8 = lane & 7;
    const int aoff72  = (((quad & 1) << 3) + r8) * 72 + ((quad >> 1) << 3);
    const int aoff136 = (((quad & 1) << 3) + r8) * 136 + ((quad >> 1) << 3);
    const int boff72  = (((quad >> 1) << 3) + r8) * 72 + ((quad & 1) << 3);
    const int rw0 = w * 16 + grp;
    const int rw1 = rw0 + 8;
    const int gq0 = q0 + rw0;
    const int gq1 = q0 + rw1;

    const __half* qgh = g_qh + (size_t)bh * Ldim * Ddim;
    const __half* kgh = g_kh + (size_t)bh * Ldim * Ddim;
    const __half* vgh = g_vh + (size_t)bh * Ddim * Ldim;  // [d][l]
    const size_t sb = ((size_t)bh << 20);
    const float* prevb = prev + sb + (size_t)(q0 + w * 16) * Ldim;

    auto issueK = [&](int kt, int s) {
        __half* dst = fKh + s * 64 * 72;
        #pragma unroll
        for (int p = 0; p < 4; p++) {
            const int cid = tid + p * 128;
            const int r = cid >> 3;
            const int cc = (cid & 7) << 3;
            cp16(&dst[r * 72 + cc], kgh + (size_t)(kt + r) * Ddim + cc);
        }
        CP_COMMIT();
    };
    auto issueV = [&](int kt) {
        #pragma unroll
        for (int p = 0; p < 4; p++) {
            const int cid = tid + p * 128;
            const int r = cid >> 3;
            const int cc = (cid & 7) << 3;
            cp16(&fVh[r * 72 + cc], vgh + (size_t)r * Ldim + kt + cc);
        }
        CP_COMMIT();
    };
    auto issueP = [&](int kt) {
        #pragma unroll
        for (int j = 0; j < 8; j++) {
            const int cid = j * 32 + lane;
            const int r = cid >> 4;
            const int c4 = (cid & 15) << 2;
            cp16(&fP[(w * 16 + r) * 68 + c4], prevb + (size_t)r * Ldim + kt + c4);
        }
        CP_COMMIT();
    };

    // Q tile once (plain stores; ordered by the first __syncthreads)
    #pragma unroll
    for (int p = 0; p < 4; p++) {
        const int cid = tid + p * 128;
        const int m = cid >> 3;
        const int cc = (cid & 7) << 3;
        *(uint4*)&uQh[m * 72 + cc] = *(const uint4*)(qgh + (size_t)(q0 + m) * Ddim + cc);
    }

    // Prologue groups: FIFO [P0, K0]
    issueP(0);
    issueK(0, 0);

    const int vl0 = mask[(bh & 3) * Ldim + gq0];
    const int vl1 = mask[(bh & 3) * Ldim + gq1];
    const float gv = 1.f / (1.f + __expf(-gat[0]));
    const float og = 1.f - gv;

    float o[8][4];
    #pragma unroll
    for (int ni = 0; ni < 8; ni++)
        #pragma unroll
        for (int r = 0; r < 4; r++) o[ni][r] = 0.f;
    float mi0 = -1e30f, mi1 = -1e30f, li0 = 0.f, li1 = 0.f;

    for (int ti = 0; ti < 16; ti++) {
        const int kt = ti * 64;
        const int s = ti & 1;
        const bool more = (ti + 1 < 16);

        // top: drain P[t] and K[t] (oldest pending groups)
        CP_WAIT0();
        __syncthreads();               // K visible; V buffer free (PV(t-1) done)
        issueV(kt);                    // FIFO: [V(t)]
        if (more) issueK(kt + 64, s ^ 1);  // FIFO: [V(t), K(t+1)]

        // S = Q @ K^T  (stage s) — V copy in flight
        float cs[8][4];
        #pragma unroll
        for (int ni = 0; ni < 8; ni++)
            #pragma unroll
            for (int r = 0; r < 4; r++) cs[ni][r] = 0.f;

        const unsigned kBase = uKb + (unsigned)(s * 64 * 72) * 2;
        #pragma unroll
        for (int ks = 0; ks < 4; ks++) {
            const int kk = ks * 16;
            unsigned a0, a1, a2, a3;
            ldsm4(a0, a1, a2, a3, uQb + (unsigned)(w * 16 * 72 + kk + aoff72) * 2);
            unsigned bf[8][2];
            #pragma unroll
            for (int np = 0; np < 4; np++)
                ldsm4(bf[2*np][0], bf[2*np][1], bf[2*np+1][0], bf[2*np+1][1],
                      kBase + (unsigned)(np * 16 * 72 + kk + boff72) * 2);
            #pragma unroll
            for (int ni = 0; ni < 8; ni++)
                mma_f16(cs[ni][0], cs[ni][1], cs[ni][2], cs[ni][3],
                        a0, a1, a2, a3, bf[ni][0], bf[ni][1]);
        }

        // mid: V(t) done (oldest retired), K(t+1) may stay pending
        if (more) CP_WAIT1(); else CP_WAIT0();
        __syncthreads();               // V visible block-wide

        // blend with prev, write scores (streaming), mask+scale
        float m0 = -1e30f, m1 = -1e30f;
        #pragma unroll
        for (int ni = 0; ni < 8; ni++) {
            const int cl = ni * 8 + tig * 2;
            const int col = kt + cl;
            const float2 p0 = *(const float2*)&fP[rw0 * 68 + cl];
            const float2 p1 = *(const float2*)&fP[rw1 * 68 + cl];
            const float b00 = p0.x * gv + og * cs[ni][0];
            const float b01 = p0.y * gv + og * cs[ni][1];
            const float b10 = p1.x * gv + og * cs[ni][2];
            const float b11 = p1.y * gv + og * cs[ni][3];
            stcs2(scores + sb + (size_t)gq0 * Ldim + col, b00, b01);
            stcs2(scores + sb + (size_t)gq1 * Ldim + col, b10, b11);
            cs[ni][0] = (col     < vl0) ? b00 * 0.125f : -1e30f;
            cs[ni][1] = (col + 1 < vl0) ? b01 * 0.125f : -1e30f;
            cs[ni][2] = (col     < vl1) ? b10 * 0.125f : -1e30f;
            cs[ni][3] = (col + 1 < vl1) ? b11 * 0.125f : -1e30f;
            m0 = fmaxf(m0, fmaxf(cs[ni][0], cs[ni][1]));
            m1 = fmaxf(m1, fmaxf(cs[ni][2], cs[ni][3]));
        }
        m0 = fmaxf(m0, __shfl_xor_sync(0xffffffffu, m0, 1));
        m0 = fmaxf(m0, __shfl_xor_sync(0xffffffffu, m0, 2));
        m1 = fmaxf(m1, __shfl_xor_sync(0xffffffffu, m1, 1));
        m1 = fmaxf(m1, __shfl_xor_sync(0xffffffffu, m1, 2));

        const float mn0 = fmaxf(mi0, m0);
        const float mn1 = fmaxf(mi1, m1);
        const float cr0 = __expf(mi0 - mn0);
        const float cr1 = __expf(mi1 - mn1);
        li0 *= cr0; li1 *= cr1;
        #pragma unroll
        for (int ni = 0; ni < 8; ni++) {
            o[ni][0] *= cr0; o[ni][1] *= cr0;
            o[ni][2] *= cr1; o[ni][3] *= cr1;
        }
        mi0 = mn0; mi1 = mn1;

        // P = exp(s - m) -> half2 into uP (warp-local rows)
        #pragma unroll
        for (int ni = 0; ni < 8; ni++) {
            const float p00 = __expf(cs[ni][0] - mn0);
            const float p01 = __expf(cs[ni][1] - mn0);
            const float p10 = __expf(cs[ni][2] - mn1);
            const float p11 = __expf(cs[ni][3] - mn1);
            li0 += p00 + p01;
            li1 += p10 + p11;
            const int pc = ni * 4 + tig;
            uP[rw0 * 68 + pc] = f2h2(p00, p01);
            uP[rw1 * 68 + pc] = f2h2(p10, p11);
        }
        __syncwarp();

        // O += P @ V
        #pragma unroll
        for (int ks = 0; ks < 4; ks++) {
            const int kk = ks * 16;
            unsigned a0, a1, a2, a3;
            ldsm4(a0, a1, a2, a3, uPb + (unsigned)(w * 16 * 136 + kk + aoff136) * 2);
            unsigned bf[8][2];
            #pragma unroll
            for (int np = 0; np < 4; np++)
                ldsm4(bf[2*np][0], bf[2*np][1], bf[2*np+1][0], bf[2*np+1][1],
                      uVb + (unsigned)(np * 16 * 72 + kk + boff72) * 2);
            #pragma unroll
            for (int ni = 0; ni < 8; ni++)
                mma_f16(o[ni][0], o[ni][1], o[ni][2], o[ni][3],
                        a0, a1, a2, a3, bf[ni][0], bf[ni][1]);
        }

        // P refill for next tile (warp-local rows, no barrier needed)
        if (more) issueP(kt + 64);
    }

    li0 += __shfl_xor_sync(0xffffffffu, li0, 1);
    li0 += __shfl_xor_sync(0xffffffffu, li0, 2);
    li1 += __shfl_xor_sync(0xffffffffu, li1, 1);
    li1 += __shfl_xor_sync(0xffffffffu, li1, 2);
    const float inv0 = 1.f / li0;
    const float inv1 = 1.f / li1;

    __half* ab = g_atth + (size_t)bh * Ldim * Ddim;
    #pragma unroll
    for (int ni = 0; ni < 8; ni++) {
        const int d = ni * 8 + tig * 2;
        *(__half2*)(ab + (size_t)gq0 * Ddim + d) =
            __float22half2_rn(make_float2(o[ni][0] * inv0, o[ni][1] * inv0));
        *(__half2*)(ab + (size_t)gq1 * Ddim + d) =
            __float22half2_rn(make_float2(o[ni][2] * inv1, o[ni][3] * inv1));
    }
}

// ---------------------------------------------------------------------------
// Launch.  Inputs: queries, keys, values, prev, mask(int32),
//   Wq_w, Wq_b, Wk_w, Wk_b, Wv_w, Wv_b, Wo_w, Wo_b, gat
// Output: [out (4M floats) | scores (64M floats)]
// ---------------------------------------------------------------------------
extern "C" void kernel_launch(void* const* d_in, const int* in_sizes, int n_in,
                              void* d_out, int out_size)
{
    (void)in_sizes; (void)n_in; (void)out_size;
    const float* queries = (const float*)d_in[0];
    const float* keys    = (const float*)d_in[1];
    const float* values  = (const float*)d_in[2];
    const float* prev    = (const float*)d_in[3];
    const int*   mask    = (const int*)d_in[4];
    const float* Wq_w = (const float*)d_in[5];
    const float* Wq_b = (const float*)d_in[6];
    const float* Wk_w = (const float*)d_in[7];
    const float* Wk_b = (const float*)d_in[8];
    const float* Wv_w = (const float*)d_in[9];
    const float* Wv_b = (const float*)d_in[10];
    const float* Wo_w = (const float*)d_in[11];
    const float* Wo_b = (const float*)d_in[12];
    const float* gat  = (const float*)d_in[13];

    float* out    = (float*)d_out;
    float* scores = out + (size_t)Bdim * Ldim * HIDdim;

    cudaFuncSetAttribute(fused_attn,
                         cudaFuncAttributeMaxDynamicSharedMemorySize, SMEM_FUSED);
    cudaFuncSetAttribute(qkv_gemm,
                         cudaFuncAttributeMaxDynamicSharedMemorySize, GEMM_SMEM);
    cudaFuncSetAttribute(out_gemm,
                         cudaFuncAttributeMaxDynamicSharedMemorySize, GEMM_SMEM);

    conv_half<<<16384, 256>>>(queries, keys, values, Wq_w, Wk_w, Wv_w, Wo_w);

    qkv_gemm<<<1536, 128, GEMM_SMEM>>>(Wq_b, Wk_b, Wv_b);

    dim3 gf(16, 64);
    fused_attn<<<gf, 128, SMEM_FUSED>>>(prev, mask, gat, scores);

    dim3 gproj(8, 64);
    out_gemm<<<gproj, 128, GEMM_SMEM>>>(Wo_b, out);
}

// round 16
// speedup vs baseline: 1.0971x; 1.0971x over previous
#include <cuda_runtime.h>
#include <cuda_fp16.h>
#include <math.h>

#define Bdim 4
#define Ldim 1024
#define Hdim 16
#define Ddim 64
#define HIDdim 1024
#define BHdim (Bdim*Hdim)

// fp16 copies of GEMM operands (converted once at start)
__device__ __half h_qry[4194304];
__device__ __half h_key[4194304];
__device__ __half h_val[4194304];
__device__ __half h_wq[1048576];
__device__ __half h_wk[1048576];
__device__ __half h_wv[1048576];
__device__ __half h_wo[1048576];
// fp16 intermediates
__device__ __half g_qh[4194304];   // [BH][L][D]
__device__ __half g_kh[4194304];   // [BH][L][D]
__device__ __half g_vh[4194304];   // TRANSPOSED [BH][D][L]
__device__ __half g_atth[4194304]; // [BH][L][D]

__device__ __forceinline__ unsigned f2h2(float lo, float hi) {
    __half2 h = __float22half2_rn(make_float2(lo, hi));
    return *(unsigned*)&h;
}

__device__ __forceinline__ void mma_f16(
    float& c0, float& c1, float& c2, float& c3,
    unsigned a0, unsigned a1, unsigned a2, unsigned a3,
    unsigned b0, unsigned b1)
{
    asm volatile(
        "mma.sync.aligned.m16n8k16.row.col.f32.f16.f16.f32 "
        "{%0,%1,%2,%3}, {%4,%5,%6,%7}, {%8,%9}, {%0,%1,%2,%3};"
        : "+f"(c0), "+f"(c1), "+f"(c2), "+f"(c3)
        : "r"(a0), "r"(a1), "r"(a2), "r"(a3), "r"(b0), "r"(b1));
}

__device__ __forceinline__ void ldsm4(
    unsigned& r0, unsigned& r1, unsigned& r2, unsigned& r3, unsigned addr)
{
    asm volatile("ldmatrix.sync.aligned.m8n8.x4.shared.b16 {%0,%1,%2,%3}, [%4];"
        : "=r"(r0), "=r"(r1), "=r"(r2), "=r"(r3) : "r"(addr));
}

__device__ __forceinline__ void cp16(void* smem, const void* gmem) {
    unsigned sa = (unsigned)__cvta_generic_to_shared(smem);
    asm volatile("cp.async.cg.shared.global [%0], [%1], 16;" :: "r"(sa), "l"(gmem));
}
__device__ __forceinline__ void stcs2(float* p, float x, float y) {
    asm volatile("st.global.cs.v2.f32 [%0], {%1,%2};" :: "l"(p), "f"(x), "f"(y) : "memory");
}
#define CP_COMMIT() asm volatile("cp.async.commit_group;")
#define CP_WAIT0()  asm volatile("cp.async.wait_group 0;")
#define CP_WAIT1()  asm volatile("cp.async.wait_group 1;")
#define CP_WAIT2()  asm volatile("cp.async.wait_group 2;")

// ---------------------------------------------------------------------------
// fp32 -> fp16 conversion of all GEMM operands. 16M floats, float4/thread.
// ---------------------------------------------------------------------------
__global__ void __launch_bounds__(256) conv_half(
    const float* __restrict__ q, const float* __restrict__ k,
    const float* __restrict__ v,
    const float* __restrict__ wq, const float* __restrict__ wk,
    const float* __restrict__ wv, const float* __restrict__ wo)
{
    const size_t idx = (size_t)blockIdx.x * 256 + threadIdx.x;
    const size_t e = idx * 4;
    const float* src;
    __half* dst;
    size_t off;
    if (e < 4194304)        { src = q;  dst = h_qry; off = e; }
    else if (e < 8388608)   { src = k;  dst = h_key; off = e - 4194304; }
    else if (e < 12582912)  { src = v;  dst = h_val; off = e - 8388608; }
    else {
        const size_t e2 = e - 12582912;
        const int s = (int)(e2 >> 20);
        off = e2 & 1048575;
        src = (s == 0) ? wq : (s == 1) ? wk : (s == 2) ? wv : wo;
        dst = (s == 0) ? h_wq : (s == 1) ? h_wk : (s == 2) ? h_wv : h_wo;
    }
    const float4 f = *(const float4*)(src + off);
    *(__half2*)(dst + off)     = __float22half2_rn(make_float2(f.x, f.y));
    *(__half2*)(dst + off + 2) = __float22half2_rn(make_float2(f.z, f.w));
}

// ---------------------------------------------------------------------------
// fp16 GEMM core: block tile 128x128, 256 threads (8 warps 2m x 4n),
// warp tile 64x32 (R11's proven shape; c[4][4][4], ~128 regs).
// K=1024, k-tile 64 halves, double-buffered cp.async, ldmatrix feeds,
// SINGLE barrier per k-iteration (R11 pipeline).
// Halves W L2 traffic vs 64x128 tiles (32 instead of 64 M-block re-reads).
// ---------------------------------------------------------------------------
#define GEMM_SMEM (2 * 2 * 128 * 72 * 2)   // 73728 B

struct GemmCoreH {
    float c[4][4][4];

    template<class SrcA>
    __device__ __forceinline__ void run(
        __half* smh, SrcA srcA, const __half* __restrict__ W,
        int M0, int N0, int tid, int wm, int wn, int lane)
    {
        __half* As = smh;                  // [2][128][72]
        __half* Ws = smh + 2 * 128 * 72;   // [2][128][72]
        const unsigned uAs = (unsigned)__cvta_generic_to_shared(As);
        const unsigned uWs = (unsigned)__cvta_generic_to_shared(Ws);
        const int quad = lane >> 3, r8 = lane & 7;
        const int aoff = (((quad & 1) << 3) + r8) * 72 + ((quad >> 1) << 3);
        const int boff = (((quad >> 1) << 3) + r8) * 72 + ((quad & 1) << 3);

        #pragma unroll
        for (int mi = 0; mi < 4; mi++)
            #pragma unroll
            for (int ni = 0; ni < 4; ni++)
                #pragma unroll
                for (int r = 0; r < 4; r++) c[mi][ni][r] = 0.f;

        auto issue = [&](int kt, int s) {
            const int k0 = kt * 64;
            #pragma unroll
            for (int p = 0; p < 4; p++) {
                const int cid = tid + p * 256;
                const int m = cid >> 3;
                const int cc = (cid & 7) << 3;
                cp16(&As[(size_t)(s * 128 + m) * 72 + cc], srcA(M0 + m, k0 + cc));
            }
            #pragma unroll
            for (int p = 0; p < 4; p++) {
                const int cid = tid + p * 256;
                const int m = cid >> 3;
                const int cc = (cid & 7) << 3;
                cp16(&Ws[(size_t)(s * 128 + m) * 72 + cc],
                     W + (size_t)(N0 + m) * 1024 + k0 + cc);
            }
            CP_COMMIT();
        };

        issue(0, 0);
        for (int kt = 0; kt < 16; kt++) {
            const int s = kt & 1;
            CP_WAIT0();
            __syncthreads();
            if (kt + 1 < 16) issue(kt + 1, s ^ 1);

            const unsigned aBase = uAs + (unsigned)((s * 128 + wm * 64) * 72 + aoff) * 2;
            const unsigned bBase = uWs + (unsigned)((s * 128 + wn * 32) * 72 + boff) * 2;
            #pragma unroll
            for (int ks = 0; ks < 4; ks++) {
                const int kk = ks * 16;
                unsigned af[4][4], bf[4][2];
                #pragma unroll
                for (int mi = 0; mi < 4; mi++)
                    ldsm4(af[mi][0], af[mi][1], af[mi][2], af[mi][3],
                          aBase + (unsigned)(mi * 16 * 72 + kk) * 2);
                #pragma unroll
                for (int np = 0; np < 2; np++)
                    ldsm4(bf[2*np][0], bf[2*np][1], bf[2*np+1][0], bf[2*np+1][1],
                          bBase + (unsigned)(np * 16 * 72 + kk) * 2);
                #pragma unroll
                for (int mi = 0; mi < 4; mi++)
                    #pragma unroll
                    for (int ni = 0; ni < 4; ni++)
                        mma_f16(c[mi][ni][0], c[mi][ni][1], c[mi][ni][2], c[mi][ni][3],
                                af[mi][0], af[mi][1], af[mi][2], af[mi][3],
                                bf[ni][0], bf[ni][1]);
            }
        }
    }
};

// ---------------------------------------------------------------------------
// Merged Q/K/V projection: 768 blocks of 256 threads, z = g>>8 (256 ea).
//   z=0: g_qh = qry @ Wq^T + bq (split-head); z=1: g_kh likewise;
//   z=2: g_vh^T = Wv @ val^T + bv (transposed, bias by ROW)
// ---------------------------------------------------------------------------
__global__ void __launch_bounds__(256, 2) qkv_gemm(
    const float* __restrict__ Wq_b, const float* __restrict__ Wk_b,
    const float* __restrict__ Wv_b)
{
    extern __shared__ __half smh[];
    const int g = blockIdx.x;
    const int z = g >> 8;
    const int r = g & 255;
    const int tid = threadIdx.x;
    const int lane = tid & 31;
    const int grp = lane >> 2;
    const int tig = lane & 3;
    const int wid = tid >> 5;
    const int wm = wid >> 2;
    const int wn = wid & 3;

    const __half *A, *W;
    const float* bias;
    int M0, N0;
    if (z == 0)      { A = h_qry; W = h_wq; bias = Wq_b; M0 = (r >> 3) * 128; N0 = (r & 7) * 128; }
    else if (z == 1) { A = h_key; W = h_wk; bias = Wk_b; M0 = (r >> 3) * 128; N0 = (r & 7) * 128; }
    else             { A = h_wv;  W = h_val; bias = Wv_b; M0 = (r & 7) * 128; N0 = (r >> 3) * 128; }

    GemmCoreH gc;
    gc.run(smh, [&](int m, int k) { return (const void*)(A + (size_t)m * 1024 + k); },
           W, M0, N0, tid, wm, wn, lane);

    #pragma unroll
    for (int mi = 0; mi < 4; mi++) {
        #pragma unroll
        for (int ni = 0; ni < 4; ni++) {
            const int r0 = M0 + wm * 64 + mi * 16 + grp;
            const int r1 = r0 + 8;
            const int cn = N0 + wn * 32 + ni * 8 + tig * 2;
            if (z == 2) {
                const float bv0 = bias[r0], bv1 = bias[r1];
                const size_t base = (size_t)(cn >> 10) * 1048576 + (cn & 1023);
                *(__half2*)(g_vh + base + (size_t)r0 * 1024) =
                    __float22half2_rn(make_float2(gc.c[mi][ni][0] + bv0, gc.c[mi][ni][1] + bv0));
                *(__half2*)(g_vh + base + (size_t)r1 * 1024) =
                    __float22half2_rn(make_float2(gc.c[mi][ni][2] + bv1, gc.c[mi][ni][3] + bv1));
            } else {
                __half* dst = (z == 0) ? g_qh : g_kh;
                const float bv0 = bias[cn], bv1 = bias[cn + 1];
                const int h = cn >> 6, d = cn & 63;
                const int bi0 = r0 >> 10, l0 = r0 & 1023;
                const int bi1 = r1 >> 10, l1 = r1 & 1023;
                *(__half2*)(dst + (((size_t)(bi0 * Hdim + h)) * Ldim + l0) * Ddim + d) =
                    __float22half2_rn(make_float2(gc.c[mi][ni][0] + bv0, gc.c[mi][ni][1] + bv1));
                *(__half2*)(dst + (((size_t)(bi1 * Hdim + h)) * Ldim + l1) * Ddim + d) =
                    __float22half2_rn(make_float2(gc.c[mi][ni][2] + bv0, gc.c[mi][ni][3] + bv1));
            }
        }
    }
}

// ---------------------------------------------------------------------------
// Output projection: out = merge_heads(g_atth) @ Wo^T + bo (fp32 out)
// ---------------------------------------------------------------------------
__global__ void __launch_bounds__(256, 2) out_gemm(
    const float* __restrict__ bias,
    float* __restrict__ Cout)
{
    extern __shared__ __half smh[];
    const int M0 = blockIdx.y * 128;
    const int N0 = blockIdx.x * 128;
    const int tid = threadIdx.x;
    const int lane = tid & 31;
    const int grp = lane >> 2;
    const int tig = lane & 3;
    const int wid = tid >> 5;
    const int wm = wid >> 2;
    const int wn = wid & 3;

    GemmCoreH gc;
    gc.run(smh,
        [&](int m, int k) {
            const int bi = m >> 10, l = m & 1023;
            const int h = k >> 6, d = k & 63;
            return (const void*)(g_atth + (((size_t)(bi * Hdim + h)) * Ldim + l) * Ddim + d);
        },
        h_wo, M0, N0, tid, wm, wn, lane);

    #pragma unroll
    for (int mi = 0; mi < 4; mi++) {
        #pragma unroll
        for (int ni = 0; ni < 4; ni++) {
            const int r0 = M0 + wm * 64 + mi * 16 + grp;
            const int r1 = r0 + 8;
            const int cn = N0 + wn * 32 + ni * 8 + tig * 2;
            const float bv0 = bias[cn], bv1 = bias[cn + 1];
            *(float2*)(Cout + (size_t)r0 * 1024 + cn) =
                make_float2(gc.c[mi][ni][0] + bv0, gc.c[mi][ni][1] + bv1);
            *(float2*)(Cout + (size_t)r1 * 1024 + cn) =
                make_float2(gc.c[mi][ni][2] + bv0, gc.c[mi][ni][3] + bv1);
        }
    }
}

// ---------------------------------------------------------------------------
// Fused flash attention: EXACT R11 (best measured config — frozen).
// 64-query blocks, 128 threads (4 warps x 16 rows). K/V double-buffered,
// prev/P warp-local, 2 __syncthreads per key-tile. Groups FIFO: K, V, P.
// ---------------------------------------------------------------------------
#define SMEM_FUSED ((64*72 * 5) * 2 + 64*68*4)   // 63488 B

__global__ void __launch_bounds__(128, 3) fused_attn(
    const float* __restrict__ prev,
    const int* __restrict__ mask,
    const float* __restrict__ gat,
    float* __restrict__ scores)
{
    extern __shared__ __half smh[];
    __half* uQh = smh;                      // [64][72]
    __half* fKh = uQh + 64 * 72;            // [2][64][72] K tiles [j][d]
    __half* fVh = fKh + 2 * 64 * 72;        // [2][64][72] V^T tiles [d][j]
    float*  fP  = (float*)(fVh + 2 * 64 * 72);  // [64][68] prev fp32 / P half2
    unsigned* uP = (unsigned*)fP;

    const unsigned uQb = (unsigned)__cvta_generic_to_shared(uQh);
    const unsigned uKb = (unsigned)__cvta_generic_to_shared(fKh);
    const unsigned uVb = (unsigned)__cvta_generic_to_shared(fVh);
    const unsigned uPb = (unsigned)__cvta_generic_to_shared(fP);

    const int bh = blockIdx.y;
    const int q0 = blockIdx.x * 64;
    const int tid = threadIdx.x;
    const int w = tid >> 5;
    const int lane = tid & 31;
    const int grp = lane >> 2;
    const int tig = lane & 3;
    const int quad = lane >> 3, r8 = lane & 7;
    const int aoff72  = (((quad & 1) << 3) + r8) * 72 + ((quad >> 1) << 3);
    const int aoff136 = (((quad & 1) << 3) + r8) * 136 + ((quad >> 1) << 3);
    const int boff72  = (((quad >> 1) << 3) + r8) * 72 + ((quad & 1) << 3);
    const int rw0 = w * 16 + grp;
    const int rw1 = rw0 + 8;
    const int gq0 = q0 + rw0;
    const int gq1 = q0 + rw1;

    const __half* qgh = g_qh + (size_t)bh * Ldim * Ddim;
    const __half* kgh = g_kh + (size_t)bh * Ldim * Ddim;
    const __half* vgh = g_vh + (size_t)bh * Ddim * Ldim;  // [d][l]
    const size_t sb = ((size_t)bh << 20);
    const float* prevb = prev + sb + (size_t)(q0 + w * 16) * Ldim;

    auto issueK = [&](int kt, int s) {
        __half* dst = fKh + s * 64 * 72;
        #pragma unroll
        for (int p = 0; p < 4; p++) {
            const int cid = tid + p * 128;
            const int r = cid >> 3;
            const int cc = (cid & 7) << 3;
            cp16(&dst[r * 72 + cc], kgh + (size_t)(kt + r) * Ddim + cc);
        }
        CP_COMMIT();
    };
    auto issueV = [&](int kt, int s) {
        __half* dst = fVh + s * 64 * 72;
        #pragma unroll
        for (int p = 0; p < 4; p++) {
            const int cid = tid + p * 128;
            const int r = cid >> 3;
            const int cc = (cid & 7) << 3;
            cp16(&dst[r * 72 + cc], vgh + (size_t)r * Ldim + kt + cc);
        }
        CP_COMMIT();
    };
    auto issueP = [&](int kt) {
        #pragma unroll
        for (int j = 0; j < 8; j++) {
            const int cid = j * 32 + lane;
            const int r = cid >> 4;
            const int c4 = (cid & 15) << 2;
            cp16(&fP[(w * 16 + r) * 68 + c4], prevb + (size_t)r * Ldim + kt + c4);
        }
        CP_COMMIT();
    };

    issueK(0, 0);
    issueV(0, 0);
    issueP(0);

    // Q tile once: 64 x 64 halves
    #pragma unroll
    for (int p = 0; p < 4; p++) {
        const int cid = tid + p * 128;
        const int m = cid >> 3;
        const int cc = (cid & 7) << 3;
        *(uint4*)&uQh[m * 72 + cc] = *(const uint4*)(qgh + (size_t)(q0 + m) * Ddim + cc);
    }

    const int vl0 = mask[(bh & 3) * Ldim + gq0];
    const int vl1 = mask[(bh & 3) * Ldim + gq1];
    const float gv = 1.f / (1.f + __expf(-gat[0]));
    const float og = 1.f - gv;

    float o[8][4];
    #pragma unroll
    for (int ni = 0; ni < 8; ni++)
        #pragma unroll
        for (int r = 0; r < 4; r++) o[ni][r] = 0.f;
    float mi0 = -1e30f, mi1 = -1e30f, li0 = 0.f, li1 = 0.f;

    for (int ti = 0; ti < 16; ti++) {
        const int kt = ti * 64;
        const int s = ti & 1;
        const bool more = (ti + 1 < 16);

        // pending: {K[t], V[t], P[t]} -> retire K
        CP_WAIT2();
        __syncthreads();               // K visible; prev-tile buffer reads done
        if (more) issueK(kt + 64, s ^ 1);

        // S = Q @ K^T  (stage s)
        float cs[8][4];
        #pragma unroll
        for (int ni = 0; ni < 8; ni++)
            #pragma unroll
            for (int r = 0; r < 4; r++) cs[ni][r] = 0.f;

        const unsigned kBase = uKb + (unsigned)(s * 64 * 72) * 2;
        #pragma unroll
        for (int ks = 0; ks < 4; ks++) {
            const int kk = ks * 16;
            unsigned a0, a1, a2, a3;
            ldsm4(a0, a1, a2, a3, uQb + (unsigned)(w * 16 * 72 + kk + aoff72) * 2);
            unsigned bf[8][2];
            #pragma unroll
            for (int np = 0; np < 4; np++)
                ldsm4(bf[2*np][0], bf[2*np][1], bf[2*np+1][0], bf[2*np+1][1],
                      kBase + (unsigned)(np * 16 * 72 + kk + boff72) * 2);
            #pragma unroll
            for (int ni = 0; ni < 8; ni++)
                mma_f16(cs[ni][0], cs[ni][1], cs[ni][2], cs[ni][3],
                        a0, a1, a2, a3, bf[ni][0], bf[ni][1]);
        }

        // pending: {V[t], P[t], (K[t+1])} -> retire V
        if (more) CP_WAIT2(); else CP_WAIT1();
        __syncthreads();               // V visible block-wide
        if (more) issueV(kt + 64, s ^ 1);

        // pending: {P[t], (K[t+1], V[t+1])} -> retire P (own-warp data)
        if (more) CP_WAIT2(); else CP_WAIT0();

        // blend with prev, write scores (streaming), mask+scale
        float m0 = -1e30f, m1 = -1e30f;
        #pragma unroll
        for (int ni = 0; ni < 8; ni++) {
            const int cl = ni * 8 + tig * 2;
            const int col = kt + cl;
            const float2 p0 = *(const float2*)&fP[rw0 * 68 + cl];
            const float2 p1 = *(const float2*)&fP[rw1 * 68 + cl];
            const float b00 = p0.x * gv + og * cs[ni][0];
            const float b01 = p0.y * gv + og * cs[ni][1];
            const float b10 = p1.x * gv + og * cs[ni][2];
            const float b11 = p1.y * gv + og * cs[ni][3];
            stcs2(scores + sb + (size_t)gq0 * Ldim + col, b00, b01);
            stcs2(scores + sb + (size_t)gq1 * Ldim + col, b10, b11);
            cs[ni][0] = (col     < vl0) ? b00 * 0.125f : -1e30f;
            cs[ni][1] = (col + 1 < vl0) ? b01 * 0.125f : -1e30f;
            cs[ni][2] = (col     < vl1) ? b10 * 0.125f : -1e30f;
            cs[ni][3] = (col + 1 < vl1) ? b11 * 0.125f : -1e30f;
            m0 = fmaxf(m0, fmaxf(cs[ni][0], cs[ni][1]));
            m1 = fmaxf(m1, fmaxf(cs[ni][2], cs[ni][3]));
        }
        m0 = fmaxf(m0, __shfl_xor_sync(0xffffffffu, m0, 1));
        m0 = fmaxf(m0, __shfl_xor_sync(0xffffffffu, m0, 2));
        m1 = fmaxf(m1, __shfl_xor_sync(0xffffffffu, m1, 1));
        m1 = fmaxf(m1, __shfl_xor_sync(0xffffffffu, m1, 2));

        const float mn0 = fmaxf(mi0, m0);
        const float mn1 = fmaxf(mi1, m1);
        const float cr0 = __expf(mi0 - mn0);
        const float cr1 = __expf(mi1 - mn1);
        li0 *= cr0; li1 *= cr1;
        #pragma unroll
        for (int ni = 0; ni < 8; ni++) {
            o[ni][0] *= cr0; o[ni][1] *= cr0;
            o[ni][2] *= cr1; o[ni][3] *= cr1;
        }
        mi0 = mn0; mi1 = mn1;

        // P = exp(s - m) -> half2 into uP (warp-local rows)
        #pragma unroll
        for (int ni = 0; ni < 8; ni++) {
            const float p00 = __expf(cs[ni][0] - mn0);
            const float p01 = __expf(cs[ni][1] - mn0);
            const float p10 = __expf(cs[ni][2] - mn1);
            const float p11 = __expf(cs[ni][3] - mn1);
            li0 += p00 + p01;
            li1 += p10 + p11;
            const int pc = ni * 4 + tig;
            uP[rw0 * 68 + pc] = f2h2(p00, p01);
            uP[rw1 * 68 + pc] = f2h2(p10, p11);
        }
        __syncwarp();

        // O += P @ V (P rows warp-local; V stage s block-visible via sync#2)
        const unsigned vBase = uVb + (unsigned)(s * 64 * 72) * 2;
        #pragma unroll
        for (int ks = 0; ks < 4; ks++) {
            const int kk = ks * 16;
            unsigned a0, a1, a2, a3;
            ldsm4(a0, a1, a2, a3, uPb + (unsigned)(w * 16 * 136 + kk + aoff136) * 2);
            unsigned bf[8][2];
            #pragma unroll
            for (int np = 0; np < 4; np++)
                ldsm4(bf[2*np][0], bf[2*np][1], bf[2*np+1][0], bf[2*np+1][1],
                      vBase + (unsigned)(np * 16 * 72 + kk + boff72) * 2);
            #pragma unroll
            for (int ni = 0; ni < 8; ni++)
                mma_f16(o[ni][0], o[ni][1], o[ni][2], o[ni][3],
                        a0, a1, a2, a3, bf[ni][0], bf[ni][1]);
        }

        // P buffer fully consumed by this warp -> refill for next tile, no bar
        if (more) issueP(kt + 64);
    }

    li0 += __shfl_xor_sync(0xffffffffu, li0, 1);
    li0 += __shfl_xor_sync(0xffffffffu, li0, 2);
    li1 += __shfl_xor_sync(0xffffffffu, li1, 1);
    li1 += __shfl_xor_sync(0xffffffffu, li1, 2);
    const float inv0 = 1.f / li0;
    const float inv1 = 1.f / li1;

    __half* ab = g_atth + (size_t)bh * Ldim * Ddim;
    #pragma unroll
    for (int ni = 0; ni < 8; ni++) {
        const int d = ni * 8 + tig * 2;
        *(__half2*)(ab + (size_t)gq0 * Ddim + d) =
            __float22half2_rn(make_float2(o[ni][0] * inv0, o[ni][1] * inv0));
        *(__half2*)(ab + (size_t)gq1 * Ddim + d) =
            __float22half2_rn(make_float2(o[ni][2] * inv1, o[ni][3] * inv1));
    }
}

// ---------------------------------------------------------------------------
// Launch.  Inputs: queries, keys, values, prev, mask(int32),
//   Wq_w, Wq_b, Wk_w, Wk_b, Wv_w, Wv_b, Wo_w, Wo_b, gat
// Output: [out (4M floats) | scores (64M floats)]
// ---------------------------------------------------------------------------
extern "C" void kernel_launch(void* const* d_in, const int* in_sizes, int n_in,
                              void* d_out, int out_size)
{
    (void)in_sizes; (void)n_in; (void)out_size;
    const float* queries = (const float*)d_in[0];
    const float* keys    = (const float*)d_in[1];
    const float* values  = (const float*)d_in[2];
    const float* prev    = (const float*)d_in[3];
    const int*   mask    = (const int*)d_in[4];
    const float* Wq_w = (const float*)d_in[5];
    const float* Wq_b = (const float*)d_in[6];
    const float* Wk_w = (const float*)d_in[7];
    const float* Wk_b = (const float*)d_in[8];
    const float* Wv_w = (const float*)d_in[9];
    const float* Wv_b = (const float*)d_in[10];
    const float* Wo_w = (const float*)d_in[11];
    const float* Wo_b = (const float*)d_in[12];
    const float* gat  = (const float*)d_in[13];

    float* out    = (float*)d_out;
    float* scores = out + (size_t)Bdim * Ldim * HIDdim;

    cudaFuncSetAttribute(fused_attn,
                         cudaFuncAttributeMaxDynamicSharedMemorySize, SMEM_FUSED);
    cudaFuncSetAttribute(qkv_gemm,
                         cudaFuncAttributeMaxDynamicSharedMemorySize, GEMM_SMEM);
    cudaFuncSetAttribute(out_gemm,
                         cudaFuncAttributeMaxDynamicSharedMemorySize, GEMM_SMEM);

    conv_half<<<16384, 256>>>(queries, keys, values, Wq_w, Wk_w, Wv_w, Wo_w);

    qkv_gemm<<<768, 256, GEMM_SMEM>>>(Wq_b, Wk_b, Wv_b);

    dim3 gf(16, 64);
    fused_attn<<<gf, 128, SMEM_FUSED>>>(prev, mask, gat, scores);

    dim3 gproj(8, 32);
    out_gemm<<<gproj, 256, GEMM_SMEM>>>(Wo_b, out);
}